// round 1
// baseline (speedup 1.0000x reference)
#include <cuda_runtime.h>
#include <stdint.h>

// Problem constants (from reference): B=128, N=256, T=1024, C=10
#define T_LEN   1024
#define N_NEUR  256
#define C_GAP   10
#define RPB     128     // rows per block (= threads per block)
#define CHUNK   64      // timesteps staged per shared-memory tile
#define STRIDE  65      // padded row stride in shared (bank-conflict-free scan)

__global__ void stca_zero_loss(float* out) {
    out[0] = 0.0f;
}

__global__ __launch_bounds__(RPB)
void stca_main_kernel(const float* __restrict__ vmem,
                      const int*   __restrict__ labels,
                      float*       __restrict__ out)
{
    __shared__ float sh[RPB * STRIDE];
    __shared__ float red[RPB];

    const int tid  = threadIdx.x;
    const int row0 = blockIdx.x * RPB;
    const int row  = row0 + tid;

    // Per-row scan state
    int   last_spike = -1000000;       // so (t - last_spike > C) at first spike
    int   nc         = 0;              // number of clusters
    int   cur_size   = 0;              // spikes in current cluster
    float cur_max    = 0.0f;           // max spike value in current cluster
    int   best_size  = 0x7fffffff;     // smallest cluster size (first occurrence wins)
    float best_max   = 0.0f;           // its max value
    float max_all    = -3.402823466e38f;

    const float4* g4 = reinterpret_cast<const float4*>(vmem + (size_t)row0 * T_LEN);
    // per-row chunk covers CHUNK floats = CHUNK/4 float4s; RPB rows per block
    // flat float4 index i4 in [0, RPB*CHUNK/4): r = i4/(CHUNK/4), c4 = i4%(CHUNK/4)

    for (int chunk = 0; chunk < T_LEN / CHUNK; ++chunk) {
        __syncthreads();   // prior chunk fully consumed before overwrite
        const int c4base = chunk * (CHUNK / 4);
        #pragma unroll
        for (int k = 0; k < (RPB * CHUNK / 4) / RPB; ++k) {   // 16 iters
            int i4 = tid + k * RPB;
            int r  = i4 >> 4;          // /(CHUNK/4)=16
            int c4 = i4 & 15;
            float4 v = g4[(size_t)r * (T_LEN / 4) + c4base + c4];
            float* dst = &sh[r * STRIDE + 4 * c4];
            dst[0] = v.x; dst[1] = v.y; dst[2] = v.z; dst[3] = v.w;
        }
        __syncthreads();

        const int   tbase  = chunk * CHUNK;
        const float* myrow = &sh[tid * STRIDE];
        #pragma unroll
        for (int c = 0; c < CHUNK; ++c) {
            float x = myrow[c];
            max_all = fmaxf(max_all, x);
            if (x >= 0.0f) {                         // spike
                int t = tbase + c;
                if (t - last_spike > C_GAP) {        // starts a new cluster
                    if (cur_size > 0 && cur_size < best_size) {
                        best_size = cur_size; best_max = cur_max;
                    }
                    nc++; cur_size = 1; cur_max = x;
                } else {                             // extends current cluster
                    cur_size++;
                    cur_max = fmaxf(cur_max, x);
                }
                last_spike = t;
            }
        }
    }
    // finalize trailing cluster
    if (cur_size > 0 && cur_size < best_size) {
        best_size = cur_size; best_max = cur_max;
    }

    // contrib per reference:
    //   target > nc  (target==1, nc==0)  -> -max_all
    //   target < nc                      -> +best_max (max over smallest cluster span;
    //                                       equals max spike value since non-spikes < 0)
    //   else                             -> 0
    const int b      = row >> 8;                 // row / N_NEUR
    const int n      = row & (N_NEUR - 1);
    const int target = (labels[b] == n) ? 1 : 0;

    float contrib = 0.0f;
    if (target > nc)      contrib = -max_all;
    else if (nc > target) contrib = best_max;

    out[1 + row] = (float)nc;                    // spike_output

    // block tree-reduction of contrib, then one atomic per block
    red[tid] = contrib;
    __syncthreads();
    #pragma unroll
    for (int s = RPB / 2; s > 0; s >>= 1) {
        if (tid < s) red[tid] += red[tid + s];
        __syncthreads();
    }
    if (tid == 0) atomicAdd(out, red[0]);
}

extern "C" void kernel_launch(void* const* d_in, const int* in_sizes, int n_in,
                              void* d_out, int out_size) {
    const float* vmem   = (const float*)d_in[0];   // [128,256,1024] f32
    // d_in[1] = vlastmem — unused by the reference forward; deliberately not read
    const int*   labels = (const int*)d_in[2];     // [128] i32
    float*       out    = (float*)d_out;           // [1 + 128*256] f32: loss, spikes

    stca_zero_loss<<<1, 1>>>(out);

    const int total_rows = 128 * 256;
    stca_main_kernel<<<total_rows / RPB, RPB>>>(vmem, labels, out);
}

// round 2
// speedup vs baseline: 1.9343x; 1.9343x over previous
#include <cuda_runtime.h>
#include <stdint.h>

// B=128, N=256, T=1024, C=10
#define T_LEN   1024
#define N_NEUR  256
#define C_GAP   10
#define WPB     8                 // warps (= rows) per block
#define THREADS (WPB * 32)
#define SEG     32                // timesteps per lane
#define RSTRIDE 33                // padded stride for transposed row in smem
#define NEGINF  (-3.402823466e38f)

struct Seg {
    int   n;            // cluster count (segment in isolation)
    int   ft, lt;       // first / last spike time (absolute)
    int   fs; float fm; // first cluster: size, max
    int   ls; float lm; // last cluster: size, max
    int   bs; float bm; // best INTERIOR cluster (smallest, earliest): size, max
};

__device__ __forceinline__ Seg seg_shfl_down(const Seg& s, int d) {
    Seg r;
    r.n  = __shfl_down_sync(0xffffffffu, s.n,  d);
    r.ft = __shfl_down_sync(0xffffffffu, s.ft, d);
    r.lt = __shfl_down_sync(0xffffffffu, s.lt, d);
    r.fs = __shfl_down_sync(0xffffffffu, s.fs, d);
    r.fm = __shfl_down_sync(0xffffffffu, s.fm, d);
    r.ls = __shfl_down_sync(0xffffffffu, s.ls, d);
    r.lm = __shfl_down_sync(0xffffffffu, s.lm, d);
    r.bs = __shfl_down_sync(0xffffffffu, s.bs, d);
    r.bm = __shfl_down_sync(0xffffffffu, s.bm, d);
    return r;
}

// Non-commutative associative merge: L is earlier in time than R.
__device__ __forceinline__ Seg seg_combine(const Seg& L, const Seg& R) {
    if (L.n == 0) return R;
    if (R.n == 0) return L;
    Seg O;
    const bool mg = (R.ft - L.lt) <= C_GAP;   // boundary clusters fuse
    O.n  = L.n + R.n - (mg ? 1 : 0);
    O.ft = L.ft;
    O.lt = R.lt;
    // combined first cluster
    if (L.n == 1 && mg) { O.fs = L.fs + R.fs; O.fm = fmaxf(L.fm, R.fm); }
    else                { O.fs = L.fs;        O.fm = L.fm; }
    // combined last cluster
    if (R.n == 1 && mg) { O.ls = L.ls + R.ls; O.lm = fmaxf(L.lm, R.lm); }
    else                { O.ls = R.ls;        O.lm = R.lm; }
    // interior best — fold candidates in time order, strict-less so earlier wins ties
    int bs = L.bs; float bm = L.bm;
    if (mg) {
        if (L.n > 1 && R.n > 1) {            // fused boundary cluster is interior
            int ms = L.ls + R.fs; float mm = fmaxf(L.lm, R.fm);
            if (ms < bs) { bs = ms; bm = mm; }
        }
    } else {
        if (L.n > 1) { if (L.ls < bs) { bs = L.ls; bm = L.lm; } } // L's last now interior
        if (R.n > 1) { if (R.fs < bs) { bs = R.fs; bm = R.fm; } } // R's first now interior
    }
    if (R.bs < bs) { bs = R.bs; bm = R.bm; }
    O.bs = bs; O.bm = bm;
    return O;
}

__global__ void stca_zero_loss(float* out) { out[0] = 0.0f; }

__global__ __launch_bounds__(THREADS)
void stca_main_kernel(const float* __restrict__ vmem,
                      const int*   __restrict__ labels,
                      float*       __restrict__ out)
{
    __shared__ float sh[WPB][SEG * RSTRIDE];     // 8 * 1056 * 4B = 33 KB
    __shared__ float warp_contrib[WPB];

    const int tid = threadIdx.x;
    const int w   = tid >> 5;
    const int l   = tid & 31;
    const int row = blockIdx.x * WPB + w;

    // ---- coalesced load of this warp's row, stored transposed:
    //      element t  ->  sh[w][(t%32)*33 + t/32]
    {
        const float4* g4 = reinterpret_cast<const float4*>(vmem + (size_t)row * T_LEN);
        float* shw = sh[w];
        #pragma unroll
        for (int m = 0; m < 8; ++m) {
            int i4 = l + m * 32;                 // float4 index within row
            float4 v = g4[i4];
            // t = 4*i4; for j<4: (t+j)%32 = 4*(l&7)+j, (t+j)/32 = (l>>3) + 4*m
            int base = (4 * (l & 7)) * RSTRIDE + (l >> 3) + 4 * m;
            shw[base              ] = v.x;
            shw[base +     RSTRIDE] = v.y;
            shw[base + 2 * RSTRIDE] = v.z;
            shw[base + 3 * RSTRIDE] = v.w;
        }
    }
    __syncwarp();

    // ---- per-lane segment scan over timesteps [32l, 32l+32)
    Seg S;
    S.n = 0; S.ft = 0; S.lt = -1000000;
    S.fs = 0; S.fm = 0.f; S.ls = 0; S.lm = 0.f;
    S.bs = 0x7fffffff; S.bm = 0.f;
    int   cs = 0;          // open cluster size
    float cm = NEGINF;     // open cluster max
    float maxall = NEGINF;

    const float* shw = sh[w];
    const int tbase = l * SEG;
    #pragma unroll
    for (int k = 0; k < SEG; ++k) {
        float x = shw[k * RSTRIDE + l];          // conflict-free (bank = (k+l)%32)
        maxall = fmaxf(maxall, x);
        if (x >= 0.0f) {                         // spike
            int t = tbase + k;
            if (t - S.lt > C_GAP) {              // new cluster starts (rare branch)
                if (S.n == 1)      { S.fs = cs; S.fm = cm; }
                else if (S.n >= 2) { if (cs < S.bs) { S.bs = cs; S.bm = cm; } }
                S.n++;
                cs = 0; cm = NEGINF;
                if (S.n == 1) S.ft = t;
            }
            cs++;
            cm = fmaxf(cm, x);
            S.lt = t;
        }
    }
    if (S.n == 1) { S.fs = cs; S.fm = cm; }      // single cluster: first == last
    S.ls = cs; S.lm = cm;

    // ---- warp reductions
    #pragma unroll
    for (int d = 16; d > 0; d >>= 1)
        maxall = fmaxf(maxall, __shfl_xor_sync(0xffffffffu, maxall, d));
    #pragma unroll
    for (int d = 1; d < 32; d <<= 1) {
        Seg R = seg_shfl_down(S, d);
        S = seg_combine(S, R);                   // lane 0 ends with full-row summary
    }

    if (l == 0) {
        const int nc = S.n;
        out[1 + row] = (float)nc;                // spike_output

        const int b      = row >> 8;
        const int nn     = row & (N_NEUR - 1);
        const int target = (labels[b] == nn) ? 1 : 0;

        float contrib = 0.0f;
        if (nc == 0) {
            if (target) contrib = -maxall;       // target > nc
        } else if (nc > target) {
            // smallest cluster over ALL clusters (time order, earlier wins ties):
            int bs = S.fs; float bm = S.fm;
            if (S.bs < bs)            { bs = S.bs; bm = S.bm; }
            if (nc > 1 && S.ls < bs)  { bs = S.ls; bm = S.lm; }
            contrib = bm;                        // span-max == max spike value (spikes >= 0 > non-spikes)
        }
        warp_contrib[w] = contrib;
    }
    __syncthreads();
    if (tid == 0) {
        float s = 0.0f;
        #pragma unroll
        for (int i = 0; i < WPB; ++i) s += warp_contrib[i];
        atomicAdd(out, s);
    }
}

extern "C" void kernel_launch(void* const* d_in, const int* in_sizes, int n_in,
                              void* d_out, int out_size) {
    const float* vmem   = (const float*)d_in[0];   // [128,256,1024] f32
    // d_in[1] = vlastmem — unused by the reference forward; deliberately not read
    const int*   labels = (const int*)d_in[2];     // [128] i32
    float*       out    = (float*)d_out;           // [1 + 128*256] f32

    stca_zero_loss<<<1, 1>>>(out);

    const int total_rows = 128 * 256;              // 32768
    stca_main_kernel<<<total_rows / WPB, THREADS>>>(vmem, labels, out);
}

// round 3
// speedup vs baseline: 2.4892x; 1.2869x over previous
#include <cuda_runtime.h>
#include <stdint.h>

// B=128, N=256, T=1024, C=10
#define T_LEN   1024
#define N_NEUR  256
#define C_GAP   10
#define WPB     8
#define THREADS (WPB * 32)
#define NEGINF  (-3.402823466e38f)
#define BIGI    0x7fffffff

// Segment summary (integer-only; values resolved in phase 2)
// Invariants: first cluster begins at ft; last cluster ends at lt.
struct Seg {
    int n;            // cluster count
    int ft, lt;       // first / last spike time
    int fs, fe;       // first cluster: size, end time
    int ls, lb;       // last  cluster: size, begin time
    int bs, bb, be;   // best interior cluster (smallest, earliest): size, begin, end
};

__device__ __forceinline__ Seg shfl_seg(const Seg& s, int d) {
    Seg r;
    r.n  = __shfl_down_sync(0xffffffffu, s.n,  d);
    r.ft = __shfl_down_sync(0xffffffffu, s.ft, d);
    r.lt = __shfl_down_sync(0xffffffffu, s.lt, d);
    r.fs = __shfl_down_sync(0xffffffffu, s.fs, d);
    r.fe = __shfl_down_sync(0xffffffffu, s.fe, d);
    r.ls = __shfl_down_sync(0xffffffffu, s.ls, d);
    r.lb = __shfl_down_sync(0xffffffffu, s.lb, d);
    r.bs = __shfl_down_sync(0xffffffffu, s.bs, d);
    r.bb = __shfl_down_sync(0xffffffffu, s.bb, d);
    r.be = __shfl_down_sync(0xffffffffu, s.be, d);
    return r;
}

// Non-commutative merge, L earlier than R. Ties: earliest cluster wins (strict <,
// candidates folded in time order).
__device__ __forceinline__ Seg combine(const Seg& L, const Seg& R) {
    if (L.n == 0) return R;
    if (R.n == 0) return L;
    Seg O;
    const bool mg = (R.ft - L.lt) <= C_GAP;      // boundary clusters fuse
    O.n  = L.n + R.n - (mg ? 1 : 0);
    O.ft = L.ft; O.lt = R.lt;
    if (L.n == 1 && mg) { O.fs = L.fs + R.fs; O.fe = R.fe; }
    else                { O.fs = L.fs;        O.fe = L.fe; }
    if (R.n == 1 && mg) { O.ls = L.ls + R.ls; O.lb = L.lb; }
    else                { O.ls = R.ls;        O.lb = R.lb; }
    int bs = L.bs, bb = L.bb, be = L.be;
    if (mg) {
        if (L.n > 1 && R.n > 1) {                // fused boundary cluster is interior
            int ms = L.ls + R.fs;
            if (ms < bs) { bs = ms; bb = L.lb; be = R.fe; }
        }
    } else {
        if (L.n > 1 && L.ls < bs) { bs = L.ls; bb = L.lb; be = L.lt; }
        if (R.n > 1 && R.fs < bs) { bs = R.fs; bb = R.ft; be = R.fe; }
    }
    if (R.bs < bs) { bs = R.bs; bb = R.bb; be = R.be; }
    O.bs = bs; O.bb = bb; O.be = be;
    return O;
}

__global__ void stca_zero_loss(float* out) { out[0] = 0.0f; }

__global__ __launch_bounds__(THREADS)
void stca_main_kernel(const float* __restrict__ vmem,
                      const int*   __restrict__ labels,
                      float*       __restrict__ out)
{
    __shared__ float warp_contrib[WPB];

    const int tid = threadIdx.x;
    const int w   = tid >> 5;
    const int l   = tid & 31;
    const int row = blockIdx.x * WPB + w;
    const float* rp = vmem + (size_t)row * T_LEN;

    // ---- Phase 1: coalesced read; ballot builds per-window spike masks.
    // Window k = times [32k, 32k+32); lane l keeps mask of window l.
    float maxall = NEGINF;
    unsigned m = 0;
    #pragma unroll
    for (int k = 0; k < 32; ++k) {
        float x = __ldg(rp + k * 32 + l);
        maxall = fmaxf(maxall, x);
        unsigned b = __ballot_sync(0xffffffffu, x >= 0.0f);
        if (l == k) m = b;
    }

    // ---- Per-lane structure from the mask (<=3 clusters per 32-step window)
    Seg S;
    const int tb = l * 32;
    if (m == 0) {
        S.n = 0; S.ft = 0; S.lt = 0; S.fs = 0; S.fe = 0; S.ls = 0; S.lb = 0;
        S.bs = BIGI; S.bb = 0; S.be = 0;
    } else {
        unsigned s1 = (m << 1) | (m << 2);       // shifts {1,2}
        unsigned s2 = s1 | (s1 << 2);            // {1..4}
        unsigned s3 = s2 | (s2 << 4);            // {1..8}
        unsigned spread = s3 | (s1 << 8);        // {1..10}
        unsigned starts = m & ~spread;           // spikes with no spike in prior C steps
        int n = __popc(starts);
        unsigned st1 = starts & (starts - 1);
        unsigned st2 = st1 & (st1 - 1);
        int p1 = st1 ? (__ffs(st1) - 1) : 32;
        int p2 = st2 ? (__ffs(st2) - 1) : 32;
        unsigned bmA = (p1 < 32) ? ((1u << p1) - 1u) : 0xffffffffu;
        unsigned bmB = (p2 < 32) ? ((1u << p2) - 1u) : 0xffffffffu;
        unsigned mA = m & bmA;                   // first cluster spikes
        unsigned mB = m & bmB & ~bmA;            // middle (n==3) or last (n==2) or 0
        unsigned mL = (n >= 3) ? (m & ~bmB) : ((n == 2) ? mB : mA);
        S.n  = n;
        S.ft = tb + __ffs(m) - 1;
        S.lt = tb + 31 - __clz(m);
        S.fs = __popc(mA);
        S.fe = tb + 31 - __clz(mA);
        S.ls = __popc(mL);
        S.lb = tb + __ffs(mL) - 1;
        if (n >= 3) { S.bs = __popc(mB); S.bb = tb + __ffs(mB) - 1; S.be = tb + 31 - __clz(mB); }
        else        { S.bs = BIGI;       S.bb = 0;                  S.be = 0; }
    }

    // ---- Warp reductions
    #pragma unroll
    for (int d = 16; d > 0; d >>= 1)
        maxall = fmaxf(maxall, __shfl_xor_sync(0xffffffffu, maxall, d));
    #pragma unroll
    for (int d = 1; d < 32; d <<= 1) {
        Seg R = shfl_seg(S, d);
        S = combine(S, R);                       // lane 0 ends with full-row summary
    }

    const int nc = __shfl_sync(0xffffffffu, S.n, 0);

    // Smallest cluster (first occurrence on ties), time order: first, interiors, last
    int cb = 0, ce = 0;
    if (l == 0 && nc > 0) {
        int cs = S.fs; cb = S.ft; ce = S.fe;
        if (S.bs < cs)            { cs = S.bs; cb = S.bb; ce = S.be; }
        if (nc > 1 && S.ls < cs)  { cs = S.ls; cb = S.lb; ce = S.lt; }
    }
    cb = __shfl_sync(0xffffffffu, cb, 0);
    ce = __shfl_sync(0xffffffffu, ce, 0);

    const int b      = row >> 8;
    const int nn     = row & (N_NEUR - 1);
    const int target = (labels[b] == nn) ? 1 : 0;

    float contrib = 0.0f;
    if (nc > target) {
        // ---- Phase 2: max over span [cb, ce] (L1-hit re-read, warp-uniform branch)
        float sm = NEGINF;
        const int lo = cb - l;                   // in-span: 32k - lo in [0, ce-cb]
        const unsigned width = (unsigned)(ce - cb);
        #pragma unroll
        for (int k = 0; k < 32; ++k) {
            float x = __ldg(rp + k * 32 + l);
            bool in = (unsigned)(32 * k - lo) <= width;
            sm = fmaxf(sm, in ? x : NEGINF);
        }
        #pragma unroll
        for (int d = 16; d > 0; d >>= 1)
            sm = fmaxf(sm, __shfl_xor_sync(0xffffffffu, sm, d));
        contrib = sm;                            // span max == cluster max (non-spikes < 0)
    } else if (nc == 0 && target) {
        contrib = -maxall;
    }

    if (l == 0) {
        out[1 + row] = (float)nc;                // spike_output
        warp_contrib[w] = contrib;
    }
    __syncthreads();
    if (tid == 0) {
        float s = 0.0f;
        #pragma unroll
        for (int i = 0; i < WPB; ++i) s += warp_contrib[i];
        atomicAdd(out, s);
    }
}

extern "C" void kernel_launch(void* const* d_in, const int* in_sizes, int n_in,
                              void* d_out, int out_size) {
    const float* vmem   = (const float*)d_in[0];   // [128,256,1024] f32
    // d_in[1] = vlastmem — unused by the reference forward; deliberately not read
    const int*   labels = (const int*)d_in[2];     // [128] i32
    float*       out    = (float*)d_out;           // [1 + 128*256] f32

    stca_zero_loss<<<1, 1>>>(out);

    const int total_rows = 128 * 256;              // 32768
    stca_main_kernel<<<total_rows / WPB, THREADS>>>(vmem, labels, out);
}

// round 4
// speedup vs baseline: 3.0351x; 1.2193x over previous
#include <cuda_runtime.h>
#include <stdint.h>

// B=128, N=256, T=1024, C=10
#define T_LEN   1024
#define N_NEUR  256
#define C_GAP   10
#define WPB     8
#define THREADS (WPB * 32)
#define NEGINF  (-3.402823466e38f)
#define FULL    0xffffffffu
#define MAXCL   96               // max clusters per row = ceil(1024/11)+1 = 95

__device__ float    g_loss;     // zero-initialized; reset by last block each launch
__device__ unsigned g_tick;

__global__ __launch_bounds__(THREADS)
void stca_main(const float* __restrict__ vmem,
               const int*   __restrict__ labels,
               float*       __restrict__ out)
{
    __shared__ unsigned sh_b[WPB][32];       // per-window ballots
    __shared__ unsigned sh_cl[WPB][MAXCL];   // (spikesBefore<<16)|startPos per cluster
    __shared__ float    warp_contrib[WPB];

    const int tid = threadIdx.x;
    const int w   = tid >> 5;
    const int l   = tid & 31;
    const bool lane0 = (l == 0);
    const int row = blockIdx.x * WPB + w;
    const float* rp = vmem + (size_t)row * T_LEN;

    // ---- Phase 1: single coalesced pass. Ballots -> per-window spike masks.
    float maxall = NEGINF;
    #pragma unroll
    for (int k = 0; k < 32; ++k) {
        float x = __ldg(rp + k * 32 + l);
        maxall = fmaxf(maxall, x);
        unsigned b = __ballot_sync(FULL, x >= 0.0f);
        if (lane0) sh_b[w][k] = b;
    }
    __syncwarp();
    unsigned m = sh_b[w][l];                 // spike mask of window [32l, 32l+32)

    // ---- Global cluster-start mask: spike with no spike in previous C steps.
    unsigned prev = __shfl_up_sync(FULL, m, 1);
    if (lane0) prev = 0;
    unsigned long long A  = ((unsigned long long)m << 32) | prev;
    unsigned long long t1 = (A << 1) | (A << 2);          // shifts {1,2}
    unsigned long long t2 = t1 | (t1 << 2);               // {1..4}
    unsigned long long t3 = t2 | (t2 << 4);               // {1..8}
    unsigned long long sp = t3 | (t1 << 8);               // {1..10}
    unsigned starts = m & ~(unsigned)(sp >> 32);

    const int sc = __popc(starts);
    const int nc = __reduce_add_sync(FULL, sc);

    const int b_     = row >> 8;
    const int nn     = row & (N_NEUR - 1);
    const int target = (__ldg(labels + b_) == nn) ? 1 : 0;

    float contrib = 0.0f;
    if (nc > target) {                       // warp-uniform
        if (nc == 1) {
            // single cluster: its span max == row max (spikes >= 0, rest < 0)
            #pragma unroll
            for (int d = 16; d > 0; d >>= 1)
                maxall = fmaxf(maxall, __shfl_xor_sync(FULL, maxall, d));
            contrib = maxall;
        } else {
            // ---- build cluster table: (spikes before start, start pos) per cluster
            const int pc = __popc(m);
            int ipc = pc, isc = sc;          // inclusive scans
            #pragma unroll
            for (int d = 1; d < 32; d <<= 1) {
                int vp = __shfl_up_sync(FULL, ipc, d);
                int vs = __shfl_up_sync(FULL, isc, d);
                if (l >= d) { ipc += vp; isc += vs; }
            }
            const int excl   = ipc - pc;     // spikes before my window
            int c             = isc - sc;    // clusters before my window
            const int S_tot  = __shfl_sync(FULL, ipc, 31);

            unsigned sm_ = starts;
            const int tb = l * 32;
            while (sm_) {
                int bit = __ffs(sm_) - 1;
                sm_ &= sm_ - 1;
                int sb = excl + __popc(m & ((1u << bit) - 1u));
                sh_cl[w][c] = ((unsigned)sb << 16) | (unsigned)(tb + bit);
                ++c;
            }
            if (lane0) sh_cl[w][nc] = ((unsigned)S_tot << 16) | (unsigned)T_LEN;
            __syncwarp();

            // ---- smallest cluster, earliest on ties: min over (size<<7 | idx)
            int best = 0x7fffffff;
            for (int c0 = l; c0 < nc; c0 += 32) {
                unsigned a  = sh_cl[w][c0];
                unsigned bn = sh_cl[w][c0 + 1];
                int size = (int)(bn >> 16) - (int)(a >> 16);
                best = min(best, (size << 7) | c0);
            }
            best = __reduce_min_sync(FULL, (unsigned)best);
            const int cstar = best & 127;
            const unsigned a  = sh_cl[w][cstar];
            const unsigned bn = sh_cl[w][cstar + 1];
            const int cb  = (int)(a  & 0xffffu);
            const int ceN = (int)(bn & 0xffffu);     // exclusive end
            const unsigned width = (unsigned)(ceN - cb);

            // ---- re-read only float4 blocks overlapping [cb, ceN) — L1 hits
            const float4* g4 = (const float4*)rp;
            float smax = NEGINF;
            const int ks = cb >> 7, ke = (ceN - 1) >> 7;
            for (int k = ks; k <= ke; ++k) {
                float4 v = g4[k * 32 + l];
                int t0 = k * 128 + 4 * l;
                if ((unsigned)(t0     - cb) < width) smax = fmaxf(smax, v.x);
                if ((unsigned)(t0 + 1 - cb) < width) smax = fmaxf(smax, v.y);
                if ((unsigned)(t0 + 2 - cb) < width) smax = fmaxf(smax, v.z);
                if ((unsigned)(t0 + 3 - cb) < width) smax = fmaxf(smax, v.w);
            }
            #pragma unroll
            for (int d = 16; d > 0; d >>= 1)
                smax = fmaxf(smax, __shfl_xor_sync(FULL, smax, d));
            contrib = smax;
        }
    } else if (nc == 0 && target) {
        #pragma unroll
        for (int d = 16; d > 0; d >>= 1)
            maxall = fmaxf(maxall, __shfl_xor_sync(FULL, maxall, d));
        contrib = -maxall;
    }

    if (lane0) {
        out[1 + row] = (float)nc;            // spike_output
        warp_contrib[w] = contrib;
    }
    __syncthreads();

    // ---- grid reduction: device-global accumulator + ticket (no pre-zero kernel)
    if (tid == 0) {
        float s = 0.0f;
        #pragma unroll
        for (int i = 0; i < WPB; ++i) s += warp_contrib[i];
        atomicAdd(&g_loss, s);
        __threadfence();
        unsigned t = atomicAdd(&g_tick, 1u);
        if (t == gridDim.x - 1) {            // last block: publish + reset for replay
            __threadfence();
            out[0] = g_loss;
            g_loss = 0.0f;
            g_tick = 0u;
        }
    }
}

extern "C" void kernel_launch(void* const* d_in, const int* in_sizes, int n_in,
                              void* d_out, int out_size) {
    const float* vmem   = (const float*)d_in[0];   // [128,256,1024] f32
    // d_in[1] = vlastmem — unused by the reference forward; deliberately not read
    const int*   labels = (const int*)d_in[2];     // [128] i32
    float*       out    = (float*)d_out;           // [1 + 128*256] f32

    const int total_rows = 128 * 256;              // 32768
    stca_main<<<total_rows / WPB, THREADS>>>(vmem, labels, out);
}